// round 12
// baseline (speedup 1.0000x reference)
#include <cuda_runtime.h>

#define TPB   128
#define OPT   64             // output-threads per block
#define S_OUT 128            // outputs per block (2 per oid)
#define M     11
#define T     4096
#define BB    32
#define NA    (S_OUT + 20)   // 148
#define NU    (S_OUT + 10)   // 138

__constant__ float cW[495];  // [0..10]=W0, then W1[k][l][m] at 11 + k*121 + l*11 + m

__global__ void __launch_bounds__(TPB, 7)
gmp_kernel(const float2* __restrict__ x,
           float2* __restrict__ out)
{
    __shared__ float  Ak[4][NA + 2];     // amplitude powers per k
    __shared__ float2 U  [NU + 2];       // complex samples window
    __shared__ float2 pc[OPT][M];        // k-partials from kh=1 half

    const int b   = blockIdx.y;
    const int t0  = blockIdx.x * S_OUT;
    const int tid = threadIdx.x;
    const int oid = tid & (OPT - 1);
    const int kh  = tid >> 6;            // warp-uniform: 0 or 1 (k-half owned)
    const float2* xb = x + (size_t)b * T;

    // ---- stage amplitude powers and samples (no weight staging needed!) ----
    for (int i = tid; i < NA; i += TPB) {
        int pos = t0 + i - 20;
        float re = 0.f, im = 0.f;
        if (pos >= 0) { float2 v = xb[pos]; re = v.x; im = v.y; }
        float a2 = re * re + im * im;
        float a  = sqrtf(a2);
        Ak[0][i] = a; Ak[1][i] = a2; Ak[2][i] = a2 * a; Ak[3][i] = a2 * a2;
        if (i >= 10) U[i - 10] = make_float2(re, im);   // u(t0 + (i-10) - 10) = xb[pos]
    }
    __syncthreads();

    // Outputs t = t0 + 2*oid + {0,1}; this thread covers k in {2kh, 2kh+1}
    float c0[M], c1[M];
    if (kh == 0) {
#pragma unroll
        for (int m = 0; m < M; m++) { float w = cW[m]; c0[m] = w; c1[m] = w; }
    } else {
#pragma unroll
        for (int m = 0; m < M; m++) { c0[m] = 0.f; c1[m] = 0.f; }
    }

#pragma unroll
    for (int kk = 0; kk < 2; kk++) {
        const int k = (kh << 1) + kk;     // warp-uniform
        float win[22];
#pragma unroll
        for (int s = 0; s < 22; s += 2) {
            float2 v = *(const float2*)&Ak[k][oid * 2 + s];
            win[s] = v.x; win[s + 1] = v.y;
        }
        const float* wb = cW + 11 + k * 121;   // warp-uniform base into constant bank
#pragma unroll
        for (int l = 0; l < M; l++) {
#pragma unroll
            for (int m = 0; m < M; m++) {
                float w = wb[l * 11 + m];      // uniform const load (LDCU), off the LSU
                c0[m] = fmaf(win[m + l],     w, c0[m]);
                c1[m] = fmaf(win[m + l + 1], w, c1[m]);
            }
        }
    }

    // ---- exchange k-partials ----
    if (kh == 1) {
#pragma unroll
        for (int m = 0; m < M; m++) pc[oid][m] = make_float2(c0[m], c1[m]);
    }
    __syncthreads();

    if (kh == 0) {   // combine and epilogue
        float2 ur[12];
#pragma unroll
        for (int s = 0; s < 12; s += 2) {
            float4 v = *(const float4*)&U[oid * 2 + s];
            ur[s]     = make_float2(v.x, v.y);
            ur[s + 1] = make_float2(v.z, v.w);
        }
        float ar0 = 0.f, ai0 = 0.f, ar1 = 0.f, ai1 = 0.f;
#pragma unroll
        for (int m = 0; m < M; m++) {
            float2 p = pc[oid][m];
            float t0c = c0[m] + p.x;
            float t1c = c1[m] + p.y;
            ar0 = fmaf(ur[m].x,     t0c, ar0);  ai0 = fmaf(ur[m].y,     t0c, ai0);
            ar1 = fmaf(ur[m + 1].x, t1c, ar1);  ai1 = fmaf(ur[m + 1].y, t1c, ai1);
        }
        float4* ob = (float4*)(out + (size_t)b * T + t0) + oid;
        *ob = make_float4(ar0, ai0, ar1, ai1);
    }
}

extern "C" void kernel_launch(void* const* d_in, const int* in_sizes, int n_in,
                              void* d_out, int out_size)
{
    const float2* x = (const float2*)d_in[0];   // (32, 4096, 2) f32
    // d_in[1] = h_0 (unused by reference)
    const float*  W = (const float*)d_in[2];    // (1, 495) f32
    float2* out = (float2*)d_out;               // (32, 4096, 2) f32

    // One D2D memcpy node into the constant bank (graph-capturable, deterministic)
    cudaMemcpyToSymbolAsync(cW, W, 495 * sizeof(float), 0, cudaMemcpyDeviceToDevice);

    dim3 grid(T / S_OUT, BB);                   // (32, 32) = 1024 blocks
    gmp_kernel<<<grid, TPB>>>(x, out);
}

// round 13
// speedup vs baseline: 1.0049x; 1.0049x over previous
#include <cuda_runtime.h>

#define TPB   128
#define OPT   64             // output-pair threads per block
#define S_OUT 128            // outputs per block: t0+oid and t0+oid+64
#define M     11
#define T     4096
#define BB    32
#define NAP   86             // AP window entries (i = oid + j, j<=21)
#define NUP   76             // U-pair window entries

typedef unsigned long long u64;

__device__ __forceinline__ u64 fma2(u64 a, u64 b, u64 c) {
    u64 d;
    asm("fma.rn.f32x2 %0, %1, %2, %3;" : "=l"(d) : "l"(a), "l"(b), "l"(c));
    return d;
}
__device__ __forceinline__ u64 add2(u64 a, u64 b) {
    u64 d;
    asm("add.rn.f32x2 %0, %1, %2;" : "=l"(d) : "l"(a), "l"(b));
    return d;
}

__global__ void __launch_bounds__(TPB, 5)     // cap 102 regs; 5 blocks = 20 warps/SM
gmp_kernel(const float2* __restrict__ x,
           const float*  __restrict__ W,
           float2* __restrict__ out)
{
    // AP[k][i] = ( A_k(t0+i-20), A_k(t0+i+44) )   [pair for outputs t, t+64]
    __shared__ float2 AP[4][NAP];
    __shared__ float2 UXP[NUP], UYP[NUP];          // (re,re+64), (im,im+64)
    __shared__ __align__(16) float2 wsP[4][M][12]; // duplicated weight pairs, padded
    __shared__ float2 w0p[M];
    __shared__ float2 pc[OPT][12];                 // k-partial exchange (u64 lanes)

    const int b   = blockIdx.y;
    const int t0  = blockIdx.x * S_OUT;
    const int tid = threadIdx.x;
    const int oid = tid & (OPT - 1);
    const int kh  = tid >> 6;                      // warp-uniform k-half
    const float2* xb = x + (size_t)b * T;

    // ---- stage amplitude-power pairs ----
    for (int i = tid; i < NAP; i += TPB) {
        int p1 = t0 + i - 20;
        int p2 = p1 + 64;
        float r1 = 0.f, i1 = 0.f, r2 = 0.f, i2 = 0.f;
        if (p1 >= 0) { float2 v = xb[p1]; r1 = v.x; i1 = v.y; }
        if (p2 < T)  { float2 v = xb[p2]; r2 = v.x; i2 = v.y; }
        float s1 = r1 * r1 + i1 * i1, s2 = r2 * r2 + i2 * i2;
        float a1 = sqrtf(s1), a2 = sqrtf(s2);
        AP[0][i] = make_float2(a1,      a2);
        AP[1][i] = make_float2(s1,      s2);
        AP[2][i] = make_float2(s1 * a1, s2 * a2);
        AP[3][i] = make_float2(s1 * s1, s2 * s2);
    }
    // ---- stage complex-sample pairs ----
    for (int i = tid; i < NUP; i += TPB) {
        int p1 = t0 + i - 10;
        int p2 = p1 + 64;
        float r1 = 0.f, i1 = 0.f, r2 = 0.f, i2 = 0.f;
        if (p1 >= 0) { float2 v = xb[p1]; r1 = v.x; i1 = v.y; }
        if (p2 < T)  { float2 v = xb[p2]; r2 = v.x; i2 = v.y; }
        UXP[i] = make_float2(r1, r2);
        UYP[i] = make_float2(i1, i2);
    }
    // ---- stage duplicated weights: one (k,l) row per thread ----
    if (tid < M) { float w = W[tid]; w0p[tid] = make_float2(w, w); }
    else if (tid >= 64 && tid < 108) {
        int r = tid - 64;                 // r = k*11 + l
        const float* src = W + 11 + r * 11;
        float2* dst = &wsP[r / 11][r % 11][0];
#pragma unroll
        for (int m = 0; m < M; m++) { float w = src[m]; dst[m] = make_float2(w, w); }
        dst[11] = make_float2(0.f, 0.f);
    }
    __syncthreads();

    // Output pair (t0+oid, t0+oid+64); this thread covers k in {2kh, 2kh+1}
    u64 c[M];
    if (kh == 0) {
#pragma unroll
        for (int m = 0; m < M; m++) c[m] = *(const u64*)&w0p[m];
    } else {
#pragma unroll
        for (int m = 0; m < M; m++) c[m] = 0ull;
    }

#pragma unroll
    for (int kk = 0; kk < 2; kk++) {
        const int k = (kh << 1) + kk;
        u64 win[21];                      // A_k(t-20+j) pairs, j=0..20
#pragma unroll
        for (int j = 0; j < 21; j++) win[j] = *(const u64*)&AP[k][oid + j];

        const ulonglong2* wrow0 = (const ulonglong2*)&wsP[k][0][0];
#pragma unroll
        for (int l = 0; l < M; l++) {
            const ulonglong2* wrow = wrow0 + l * 6;   // 12 float2 = 6 ulonglong2
            ulonglong2 q0 = wrow[0];                  // (w0w0, w1w1)  LDS.128
            ulonglong2 q1 = wrow[1];
            ulonglong2 q2 = wrow[2];
            ulonglong2 q3 = wrow[3];
            ulonglong2 q4 = wrow[4];
            u64 w10 = *(const u64*)&wsP[k][l][10];    // LDS.64
            c[0]  = fma2(win[l + 0],  q0.x, c[0]);
            c[1]  = fma2(win[l + 1],  q0.y, c[1]);
            c[2]  = fma2(win[l + 2],  q1.x, c[2]);
            c[3]  = fma2(win[l + 3],  q1.y, c[3]);
            c[4]  = fma2(win[l + 4],  q2.x, c[4]);
            c[5]  = fma2(win[l + 5],  q2.y, c[5]);
            c[6]  = fma2(win[l + 6],  q3.x, c[6]);
            c[7]  = fma2(win[l + 7],  q3.y, c[7]);
            c[8]  = fma2(win[l + 8],  q4.x, c[8]);
            c[9]  = fma2(win[l + 9],  q4.y, c[9]);
            c[10] = fma2(win[l + 10], w10,  c[10]);
        }
    }

    // ---- exchange k-partials ----
    if (kh == 1) {
#pragma unroll
        for (int m = 0; m < M; m++) pc[oid][m] = *(float2*)&c[m];
    }
    __syncthreads();

    if (kh == 0) {   // combine + epilogue (warps 0-1, uniform)
        u64 ar = 0ull, ai = 0ull;
#pragma unroll
        for (int m = 0; m < M; m++) {
            u64 cm = add2(c[m], *(const u64*)&pc[oid][m]);
            u64 ux = *(const u64*)&UXP[oid + m];
            u64 uy = *(const u64*)&UYP[oid + m];
            ar = fma2(ux, cm, ar);
            ai = fma2(uy, cm, ai);
        }
        float2 arf = *(float2*)&ar;
        float2 aif = *(float2*)&ai;
        float2* ob = out + (size_t)b * T + t0;
        ob[oid]      = make_float2(arf.x, aif.x);
        ob[oid + 64] = make_float2(arf.y, aif.y);
    }
}

extern "C" void kernel_launch(void* const* d_in, const int* in_sizes, int n_in,
                              void* d_out, int out_size)
{
    const float2* x = (const float2*)d_in[0];   // (32, 4096, 2) f32
    // d_in[1] = h_0 (unused by reference)
    const float*  W = (const float*)d_in[2];    // (1, 495) f32
    float2* out = (float2*)d_out;               // (32, 4096, 2) f32

    dim3 grid(T / S_OUT, BB);                   // (32, 32) = 1024 blocks
    gmp_kernel<<<grid, TPB>>>(x, W, out);
}

// round 14
// speedup vs baseline: 1.2179x; 1.2119x over previous
#include <cuda_runtime.h>

#define TPB   128
#define OPT   32              // output-quad threads per block
#define S_OUT 128             // outputs per block (4 per oid)
#define M     11
#define T     4096
#define BB    32
#define NA    (S_OUT + 20)    // 148 amplitude entries
#define NU    (S_OUT + 10)    // 138 sample entries

__global__ void __launch_bounds__(TPB, 5)   // <=102 regs, 5 blocks = 20 warps/SM
gmp_kernel(const float2* __restrict__ x,
           const float*  __restrict__ W,
           float2* __restrict__ out)
{
    __shared__ __align__(16) float  Ak[4][NA + 4];   // amplitude powers per k
    __shared__ __align__(16) float2 U[NU + 2];       // complex samples
    __shared__ __align__(16) float  wsK[4][M][12];   // W1 rows padded to 12
    __shared__ float  w0s[M];
    __shared__ __align__(16) float4 pc[3][OPT][13];  // k-partials (padded stride)

    const int b   = blockIdx.y;
    const int t0  = blockIdx.x * S_OUT;
    const int tid = threadIdx.x;
    const int oid = tid & (OPT - 1);
    const int kg  = tid >> 5;             // warp-uniform: k owned (one warp per k)
    const float2* xb = x + (size_t)b * T;

    // ---- stage amplitude powers + samples ----
    for (int i = tid; i < NA; i += TPB) {
        int pos = t0 + i - 20;
        float re = 0.f, im = 0.f;
        if (pos >= 0) { float2 v = xb[pos]; re = v.x; im = v.y; }
        float a2 = re * re + im * im;
        float a  = sqrtf(a2);
        Ak[0][i] = a; Ak[1][i] = a2; Ak[2][i] = a2 * a; Ak[3][i] = a2 * a2;
        if (i >= 10) U[i - 10] = make_float2(re, im);
    }
    // ---- stage weights: straight-line ----
    if (tid < M) w0s[tid] = W[tid];
    else if (tid >= 64 && tid < 108) {
        int r = tid - 64;                 // r = k*11 + l
        const float* src = W + 11 + r * 11;
        float* dst = &wsK[r / 11][r % 11][0];
#pragma unroll
        for (int m = 0; m < M; m++) dst[m] = src[m];
        dst[11] = 0.f;
    }
    __syncthreads();

    // Outputs t = t0 + 4*oid + r, r=0..3; this thread covers k = kg.
    // cc[m] = (c_t[m], c_{t+1}[m], c_{t+2}[m], c_{t+3}[m])  -> 44 independent chains
    float4 cc[M];
    if (kg == 0) {
#pragma unroll
        for (int m = 0; m < M; m++) { float w = w0s[m]; cc[m] = make_float4(w, w, w, w); }
    } else {
#pragma unroll
        for (int m = 0; m < M; m++) cc[m] = make_float4(0.f, 0.f, 0.f, 0.f);
    }

    {
        float win[24];                    // A_kg(t0 + 4*oid - 20 + s), s=0..23; 4-aligned
#pragma unroll
        for (int q = 0; q < 24; q += 4) {
            float4 v = *(const float4*)&Ak[kg][4 * oid + q];   // LDS.128
            win[q] = v.x; win[q + 1] = v.y; win[q + 2] = v.z; win[q + 3] = v.w;
        }
#pragma unroll
        for (int l = 0; l < M; l++) {
            float4 wa = *(const float4*)&wsK[kg][l][0];   // broadcast LDS.128
            float4 wb = *(const float4*)&wsK[kg][l][4];
            float4 wc = *(const float4*)&wsK[kg][l][8];
            const float w[11] = { wa.x, wa.y, wa.z, wa.w, wb.x, wb.y, wb.z, wb.w,
                                  wc.x, wc.y, wc.z };
#pragma unroll
            for (int m = 0; m < M; m++) {
                cc[m].x = fmaf(win[l + m + 0], w[m], cc[m].x);
                cc[m].y = fmaf(win[l + m + 1], w[m], cc[m].y);
                cc[m].z = fmaf(win[l + m + 2], w[m], cc[m].z);
                cc[m].w = fmaf(win[l + m + 3], w[m], cc[m].w);
            }
        }
    }

    // ---- exchange k-partials (kg 1..3 publish as STS.128) ----
    if (kg != 0) {
#pragma unroll
        for (int m = 0; m < M; m++) pc[kg - 1][oid][m] = cc[m];
    }
    __syncthreads();

    if (kg == 0) {   // warp 0: combine + epilogue (4 outputs per thread)
        float ur[14], ui[14];             // u(t0 + 4*oid + j - 10), j=0..13
#pragma unroll
        for (int q = 0; q < 14; q += 2) { // float2 idx 4*oid+q even -> 16B aligned
            float4 v = *(const float4*)&U[4 * oid + q];
            ur[q] = v.x; ui[q] = v.y; ur[q + 1] = v.z; ui[q + 1] = v.w;
        }
        float ar0 = 0.f, ai0 = 0.f, ar1 = 0.f, ai1 = 0.f;
        float ar2 = 0.f, ai2 = 0.f, ar3 = 0.f, ai3 = 0.f;
#pragma unroll
        for (int m = 0; m < M; m++) {
            float4 p0 = pc[0][oid][m];
            float4 p1 = pc[1][oid][m];
            float4 p2 = pc[2][oid][m];
            float c0 = cc[m].x + p0.x + p1.x + p2.x;
            float c1 = cc[m].y + p0.y + p1.y + p2.y;
            float c2 = cc[m].z + p0.z + p1.z + p2.z;
            float c3 = cc[m].w + p0.w + p1.w + p2.w;
            ar0 = fmaf(ur[m + 0], c0, ar0);  ai0 = fmaf(ui[m + 0], c0, ai0);
            ar1 = fmaf(ur[m + 1], c1, ar1);  ai1 = fmaf(ui[m + 1], c1, ai1);
            ar2 = fmaf(ur[m + 2], c2, ar2);  ai2 = fmaf(ui[m + 2], c2, ai2);
            ar3 = fmaf(ur[m + 3], c3, ar3);  ai3 = fmaf(ui[m + 3], c3, ai3);
        }
        float4* ob = (float4*)(out + (size_t)b * T + t0 + 4 * oid);
        ob[0] = make_float4(ar0, ai0, ar1, ai1);   // two float2 outputs per STG.128
        ob[1] = make_float4(ar2, ai2, ar3, ai3);
    }
}

extern "C" void kernel_launch(void* const* d_in, const int* in_sizes, int n_in,
                              void* d_out, int out_size)
{
    const float2* x = (const float2*)d_in[0];   // (32, 4096, 2) f32
    // d_in[1] = h_0 (unused by reference)
    const float*  W = (const float*)d_in[2];    // (1, 495) f32
    float2* out = (float2*)d_out;               // (32, 4096, 2) f32

    dim3 grid(T / S_OUT, BB);                   // (32, 32) = 1024 blocks
    gmp_kernel<<<grid, TPB>>>(x, W, out);
}